// round 6
// baseline (speedup 1.0000x reference)
#include <cuda_runtime.h>
#include <cstdint>

// ---------------------------------------------------------------------------
// LocationSlayerArch, round 6: L2-resident chunked pipeline.
//   k_bitify      : active-input index lists (premultiplied byte offsets)
//   k_gemm1(c)    : sparse layer-1 GEMM for t-chunk c -> g_prechunk (82MB,
//                   reused across chunks => L2-resident)
//   k_neuron1(c)  : psp+spike recurrence for chunk c, state carried in g_st*,
//                   spikes emitted as bitmasks g_sb (5MB)
//   k_final       : s1 x W2 GEMM from bitmasks + hb-sum + layer-2 recurrence
// g_pre round-trip through DRAM and g_v2part (51MB) are eliminated.
// ---------------------------------------------------------------------------

#define N_BATCH 128
#define T_SEQ   156
#define C_IN    156
#define H_DIM   1024
#define O_DIM   20
#define HB_CNT  8
#define HB_SZ   128
#define IDX_CAP 160
#define ROW_BYTES 512                 // ws row stride (128 floats)
#define CHUNK_T 78                    // 156 = 2 * 78

#define LAM_S  0.90483741803595952f
#define K_PSP  0.27182818284590452f
#define LAM_R  0.36787944117144233f
#define C_REF  -54.365636569180902f
#define C_P16  1.1253517471925912e-07f
#define C_Q16  1.8005627955081459e-06f
#define THETA  10.0f

__device__ __constant__ int c_td[39] = {
    11,25,35,4,18,30,7,2,20,37,29,12,9,33,23,16,1,6,15,21,
    27,34,39,24,17,10,31,38,28,14,3,22,32,8,19,36,5,13,26};

#define NSLAB (2 * N_BATCH * HB_CNT)          // 2048 (path,n,hb) slabs
__device__ unsigned g_idx[(size_t)2 * N_BATCH * T_SEQ * IDX_CAP];   // 25.6MB
__device__ int      g_cnt[2 * N_BATCH * T_SEQ];
__device__ float    g_prechunk[(size_t)NSLAB * CHUNK_T * HB_SZ];    // 81.8MB
__device__ float4   g_stF[NSLAB * HB_SZ];                           // 16MB.. (4 floats)
__device__ unsigned g_stH[NSLAB * HB_SZ];
__device__ unsigned g_sb[(size_t)NSLAB * T_SEQ * 4];                // 5.1MB

// ---------------------------------------------------------------------------
// K0: build active-index lists for BOTH paths. grid n, 320 threads.
// ---------------------------------------------------------------------------
__global__ void __launch_bounds__(320) k_bitify(const float* __restrict__ x) {
    extern __shared__ float xs[];                 // [C_IN][T_SEQ]
    int n = blockIdx.x;
    const float* xb = x + (size_t)n * C_IN * T_SEQ;
    for (int i = threadIdx.x; i < C_IN * T_SEQ; i += blockDim.x) xs[i] = xb[i];
    __syncthreads();

    int task = threadIdx.x;
    if (task >= 2 * T_SEQ) return;
    int path = task >= T_SEQ;
    int seq = path ? task - T_SEQ : task;
    unsigned* ob = g_idx + ((size_t)(path * N_BATCH + n) * T_SEQ + seq) * IDX_CAP;
    int cnt = 0;
    if (path == 0) {
        int t = seq;
        for (int c = 0; c < C_IN; c++)
            if (xs[c * T_SEQ + t] > 0.5f) ob[cnt++] = (unsigned)(c * ROW_BYTES);
    } else {
        int cp = seq;
        int blk = cp / 78, j2 = cp % 78;
        int pc = 2 * c_td[j2 >> 1] - 2 + (j2 & 1) + blk * 78;   // PERM[cp]
        for (int t = 0; t < T_SEQ; t++)
            if (xs[pc * T_SEQ + t] > 0.5f) ob[cnt++] = (unsigned)(t * ROW_BYTES);
    }
    while (cnt & 3) ob[cnt++] = (unsigned)(C_IN * ROW_BYTES);  // dummy zero row
    g_cnt[(path * N_BATCH + n) * T_SEQ + seq] = cnt;
}

// ---------------------------------------------------------------------------
// K1a: sparse GEMM1 for one t-chunk. grid (hb, n, path), 512 threads.
// ---------------------------------------------------------------------------
__global__ void __launch_bounds__(512) k_gemm1(const float* __restrict__ w_main,
                                               const float* __restrict__ w_loc,
                                               int t0) {
    extern __shared__ float ws[];   // [157][128]; row 156 = zeros
    int hb = blockIdx.x, n = blockIdx.y, path = blockIdx.z;
    int tid = threadIdx.x;
    const float* wa = path ? w_loc : w_main;

    for (int i = tid; i < HB_SZ * C_IN; i += 512) {
        int hl = i / C_IN, c = i % C_IN;
        ws[c * HB_SZ + hl] = wa[(size_t)(hb * HB_SZ + hl) * C_IN + c];
    }
    for (int i = tid; i < HB_SZ; i += 512) ws[C_IN * HB_SZ + i] = 0.0f;
    __syncthreads();

    uint32_t ws32;
    asm("{ .reg .u64 t; cvta.to.shared.u64 t, %1; cvt.u32.u64 %0, t; }"
        : "=r"(ws32) : "l"(ws));

    int wrp = tid >> 5, lane = tid & 31;
    uint32_t base = ws32 + lane * 16;
    float* pp = g_prechunk + (size_t)((path * N_BATCH + n) * HB_CNT + hb) * (CHUNK_T * HB_SZ);
    const int seqbase = (path * N_BATCH + n) * T_SEQ + t0;

    for (int tl = wrp; tl < CHUNK_T; tl += 16) {
        const unsigned* ib = g_idx + (size_t)(seqbase + tl) * IDX_CAP;
        int cnt = g_cnt[seqbase + tl];
        unsigned long long acc0 = 0ULL, acc1 = 0ULL;
        for (int k = 0; k < cnt; k += 4) {
            uint4 v = *(const uint4*)(ib + k);
            unsigned long long a, b;
            asm volatile("ld.shared.v2.b64 {%0,%1}, [%2];" : "=l"(a), "=l"(b) : "r"(base + v.x));
            asm("add.rn.f32x2 %0, %0, %1;" : "+l"(acc0) : "l"(a));
            asm("add.rn.f32x2 %0, %0, %1;" : "+l"(acc1) : "l"(b));
            asm volatile("ld.shared.v2.b64 {%0,%1}, [%2];" : "=l"(a), "=l"(b) : "r"(base + v.y));
            asm("add.rn.f32x2 %0, %0, %1;" : "+l"(acc0) : "l"(a));
            asm("add.rn.f32x2 %0, %0, %1;" : "+l"(acc1) : "l"(b));
            asm volatile("ld.shared.v2.b64 {%0,%1}, [%2];" : "=l"(a), "=l"(b) : "r"(base + v.z));
            asm("add.rn.f32x2 %0, %0, %1;" : "+l"(acc0) : "l"(a));
            asm("add.rn.f32x2 %0, %0, %1;" : "+l"(acc1) : "l"(b));
            asm volatile("ld.shared.v2.b64 {%0,%1}, [%2];" : "=l"(a), "=l"(b) : "r"(base + v.w));
            asm("add.rn.f32x2 %0, %0, %1;" : "+l"(acc0) : "l"(a));
            asm("add.rn.f32x2 %0, %0, %1;" : "+l"(acc1) : "l"(b));
        }
        uint2 u0 = *reinterpret_cast<uint2*>(&acc0);
        uint2 u1 = *reinterpret_cast<uint2*>(&acc1);
        float4 r;
        r.x = __uint_as_float(u0.x); r.y = __uint_as_float(u0.y);
        r.z = __uint_as_float(u1.x); r.w = __uint_as_float(u1.y);
        *(float4*)(pp + tl * HB_SZ + lane * 4) = r;
    }
}

// ---------------------------------------------------------------------------
// K1b: layer-1 recurrence for one chunk; spikes -> bitmasks.
// grid (hb, n, path), 128 threads. State carried in g_stF/g_stH.
// ---------------------------------------------------------------------------
__global__ void __launch_bounds__(HB_SZ) k_neuron1(int chunk) {
    int hb = blockIdx.x, n = blockIdx.y, path = blockIdx.z;
    int tid = threadIdx.x;
    int lane = tid & 31, wrp = tid >> 5;

    int slab = (path * N_BATCH + n) * HB_CNT + hb;
    const float* pp = g_prechunk + (size_t)slab * (CHUNK_T * HB_SZ);
    unsigned* sbout = g_sb + (size_t)slab * (T_SEQ * 4) + (chunk * CHUNK_T) * 4;

    float A, B, P, Q;
    unsigned hist;
    if (chunk == 0) {
        A = B = P = Q = 0.f; hist = 0u;
    } else {
        float4 st = g_stF[slab * HB_SZ + tid];
        A = st.x; B = st.y; P = st.z; Q = st.w;
        hist = g_stH[slab * HB_SZ + tid];
    }

    #pragma unroll 6
    for (int tl = 0; tl < CHUNK_T; tl++) {
        float acc = pp[tl * HB_SZ + tid];
        B = LAM_S * (B + A);
        A = LAM_S * A + acc;
        float u  = K_PSP * B;
        float um = u + C_REF * Q;
        unsigned spk = (um >= THETA) ? 1u : 0u;
        float s = (float)spk;
        float aged = (float)((hist >> 14) & 1u);
        Q = LAM_R * (Q + P + s) - aged * C_Q16;
        P = LAM_R * (P + s)     - aged * C_P16;
        hist = (hist << 1) | spk;
        unsigned bal = __ballot_sync(0xffffffffu, spk);
        if (lane == 0) sbout[tl * 4 + wrp] = bal;
    }

    if (chunk == 0) {
        g_stF[slab * HB_SZ + tid] = make_float4(A, B, P, Q);
        g_stH[slab * HB_SZ + tid] = hist;
    }
}

// ---------------------------------------------------------------------------
// K2: s1 x W2 from bitmasks (per-hb partials summed in ascending hb order),
// then layer-2 recurrence + output. grid 256 = (path, n), 128 threads.
// ---------------------------------------------------------------------------
#define TO (T_SEQ * O_DIM)   // 3120
__global__ void __launch_bounds__(128) k_final(float* __restrict__ out,
                                               const float* __restrict__ wb_main,
                                               const float* __restrict__ wb_loc) {
    extern __shared__ float smem[];
    float* w2s = smem;            // [1024][20], 80KB
    float* v   = smem + H_DIM * O_DIM;   // [156][20]

    int b = blockIdx.x;
    int path = b >> 7, n = b & 127;
    int tid = threadIdx.x;
    const float* wb = path ? wb_loc : wb_main;

    for (int i = tid; i < H_DIM * O_DIM; i += 128) {
        int o = i / H_DIM, h = i % H_DIM;
        w2s[h * O_DIM + o] = wb[(size_t)o * H_DIM + h];
    }
    __syncthreads();

    uint32_t w2s32;
    asm("{ .reg .u64 t; cvta.to.shared.u64 t, %1; cvt.u32.u64 %0, t; }"
        : "=r"(w2s32) : "l"(w2s));

    const unsigned* sbb = g_sb + (size_t)(path * N_BATCH + n) * HB_CNT * (T_SEQ * 4);

    for (int t = tid; t < T_SEQ; t += 128) {
        unsigned long long acc[10];
        #pragma unroll
        for (int i = 0; i < 10; i++) acc[i] = 0ULL;
        for (int hb = 0; hb < HB_CNT; hb++) {
            unsigned long long tmp[10];
            #pragma unroll
            for (int i = 0; i < 10; i++) tmp[i] = 0ULL;
            const unsigned* sm = sbb + (size_t)hb * (T_SEQ * 4) + t * 4;
            uint32_t hbbase = w2s32 + (unsigned)(hb * HB_SZ * O_DIM * 4);
            #pragma unroll
            for (int wd = 0; wd < 4; wd++) {
                unsigned m = sm[wd];
                while (m) {
                    int j = __ffs(m) - 1;
                    m &= m - 1u;
                    uint32_t row = hbbase + (unsigned)((wd * 32 + j) * (O_DIM * 4));
                    unsigned long long a, c;
                    asm volatile("ld.shared.v2.b64 {%0,%1}, [%2];" : "=l"(a), "=l"(c) : "r"(row));
                    asm("add.rn.f32x2 %0, %0, %1;" : "+l"(tmp[0]) : "l"(a));
                    asm("add.rn.f32x2 %0, %0, %1;" : "+l"(tmp[1]) : "l"(c));
                    asm volatile("ld.shared.v2.b64 {%0,%1}, [%2];" : "=l"(a), "=l"(c) : "r"(row + 16));
                    asm("add.rn.f32x2 %0, %0, %1;" : "+l"(tmp[2]) : "l"(a));
                    asm("add.rn.f32x2 %0, %0, %1;" : "+l"(tmp[3]) : "l"(c));
                    asm volatile("ld.shared.v2.b64 {%0,%1}, [%2];" : "=l"(a), "=l"(c) : "r"(row + 32));
                    asm("add.rn.f32x2 %0, %0, %1;" : "+l"(tmp[4]) : "l"(a));
                    asm("add.rn.f32x2 %0, %0, %1;" : "+l"(tmp[5]) : "l"(c));
                    asm volatile("ld.shared.v2.b64 {%0,%1}, [%2];" : "=l"(a), "=l"(c) : "r"(row + 48));
                    asm("add.rn.f32x2 %0, %0, %1;" : "+l"(tmp[6]) : "l"(a));
                    asm("add.rn.f32x2 %0, %0, %1;" : "+l"(tmp[7]) : "l"(c));
                    asm volatile("ld.shared.v2.b64 {%0,%1}, [%2];" : "=l"(a), "=l"(c) : "r"(row + 64));
                    asm("add.rn.f32x2 %0, %0, %1;" : "+l"(tmp[8]) : "l"(a));
                    asm("add.rn.f32x2 %0, %0, %1;" : "+l"(tmp[9]) : "l"(c));
                }
            }
            #pragma unroll
            for (int i = 0; i < 10; i++)
                asm("add.rn.f32x2 %0, %0, %1;" : "+l"(acc[i]) : "l"(tmp[i]));
        }
        float2* vp = (float2*)(v + t * O_DIM);
        #pragma unroll
        for (int i = 0; i < 10; i++) vp[i] = *reinterpret_cast<float2*>(&acc[i]);
    }
    __syncthreads();

    if (tid < O_DIM) {
        int o = tid;
        float* op = out + ((size_t)n * O_DIM + o) * 312 + path * T_SEQ;
        float A = 0.f, B = 0.f, P = 0.f, Q = 0.f;
        unsigned hist = 0u;
        #pragma unroll 4
        for (int t = 0; t < T_SEQ; t++) {
            float pre = v[t * O_DIM + o];
            B = LAM_S * (B + A);
            A = LAM_S * A + pre;
            float u  = K_PSP * B;
            float um = u + C_REF * Q;
            unsigned spk = (um >= THETA) ? 1u : 0u;
            float s = (float)spk;
            float aged = (float)((hist >> 14) & 1u);
            Q = LAM_R * (Q + P + s) - aged * C_Q16;
            P = LAM_R * (P + s)     - aged * C_P16;
            hist = (hist << 1) | spk;
            op[t] = s;
        }
    }
}

// ---------------------------------------------------------------------------
extern "C" void kernel_launch(void* const* d_in, const int* in_sizes, int n_in,
                              void* d_out, int out_size) {
    const float* x   = (const float*)d_in[0];
    const float* w1  = (const float*)d_in[1];
    const float* w2  = (const float*)d_in[2];
    const float* wl1 = (const float*)d_in[3];
    const float* wl2 = (const float*)d_in[4];
    float* out = (float*)d_out;

    const int SM0 = C_IN * T_SEQ * 4;                    // 97344
    const int SM1 = 157 * HB_SZ * 4;                     // 80384
    const int SM2 = (H_DIM * O_DIM + TO) * 4;            // 94400
    cudaFuncSetAttribute(k_bitify, cudaFuncAttributeMaxDynamicSharedMemorySize, SM0);
    cudaFuncSetAttribute(k_gemm1,  cudaFuncAttributeMaxDynamicSharedMemorySize, SM1);
    cudaFuncSetAttribute(k_final,  cudaFuncAttributeMaxDynamicSharedMemorySize, SM2);

    k_bitify<<<N_BATCH, 320, SM0>>>(x);

    dim3 g1(HB_CNT, N_BATCH, 2);
    k_gemm1<<<g1, 512, SM1>>>(w1, wl1, 0);
    k_neuron1<<<g1, HB_SZ>>>(0);
    k_gemm1<<<g1, 512, SM1>>>(w1, wl1, CHUNK_T);
    k_neuron1<<<g1, HB_SZ>>>(1);

    k_final<<<2 * N_BATCH, 128, SM2>>>(out, w2, wl2);
}

// round 7
// speedup vs baseline: 1.6373x; 1.6373x over previous
#include <cuda_runtime.h>
#include <cstdint>

// ---------------------------------------------------------------------------
// LocationSlayerArch, round 7: round-6 chunked pipeline + pre-transposed
// layer-1 weights (kills the 32-way STS bank conflict that dominated gemm)
// + warp-ballot bitify.
//   k_wt     : W1/Wl1 -> g_w1t[path][c][h] (one-time, L2-resident)
//   k_bitify : ballot-compacted active-index lists
//   k_gemm1  : sparse layer-1 GEMM per t-chunk -> g_prechunk (L2-resident)
//   k_neuron1: psp+spike recurrence per chunk -> bitmasks g_sb
//   k_final  : s1 x W2 GEMM from bitmasks + layer-2 recurrence + output
// ---------------------------------------------------------------------------

#define N_BATCH 128
#define T_SEQ   156
#define C_IN    156
#define H_DIM   1024
#define O_DIM   20
#define HB_CNT  8
#define HB_SZ   128
#define IDX_CAP 160
#define ROW_BYTES 512                 // ws row stride (128 floats)
#define CHUNK_T 78                    // 156 = 2 * 78

#define LAM_S  0.90483741803595952f
#define K_PSP  0.27182818284590452f
#define LAM_R  0.36787944117144233f
#define C_REF  -54.365636569180902f
#define C_P16  1.1253517471925912e-07f
#define C_Q16  1.8005627955081459e-06f
#define THETA  10.0f

__device__ __constant__ int c_td[39] = {
    11,25,35,4,18,30,7,2,20,37,29,12,9,33,23,16,1,6,15,21,
    27,34,39,24,17,10,31,38,28,14,3,22,32,8,19,36,5,13,26};

#define NSLAB (2 * N_BATCH * HB_CNT)          // 2048 (path,n,hb) slabs
__device__ unsigned g_idx[(size_t)2 * N_BATCH * T_SEQ * IDX_CAP];   // 25.6MB
__device__ int      g_cnt[2 * N_BATCH * T_SEQ];
__device__ float    g_w1t[2][C_IN * H_DIM];                         // 1.3MB
__device__ float    g_prechunk[(size_t)NSLAB * CHUNK_T * HB_SZ];    // 81.8MB
__device__ float4   g_stF[NSLAB * HB_SZ];
__device__ unsigned g_stH[NSLAB * HB_SZ];
__device__ unsigned g_sb[(size_t)NSLAB * T_SEQ * 4];                // 5.1MB

// ---------------------------------------------------------------------------
// K-1: transpose layer-1 weights: g_w1t[path][c*1024 + h] = w[h*156 + c].
// ---------------------------------------------------------------------------
__global__ void __launch_bounds__(256) k_wt(const float* __restrict__ w_main,
                                            const float* __restrict__ w_loc) {
    int i = blockIdx.x * 256 + threadIdx.x;
    if (i >= 2 * C_IN * H_DIM) return;
    int path = i / (C_IN * H_DIM);
    int r = i % (C_IN * H_DIM);
    int c = r / H_DIM, h = r % H_DIM;
    const float* w = path ? w_loc : w_main;
    g_w1t[path][r] = w[(size_t)h * C_IN + c];
}

// ---------------------------------------------------------------------------
// K0: ballot-compacted active-index lists. grid n, 256 threads = 8 warps.
// Warp handles one seq at a time (both paths).
// ---------------------------------------------------------------------------
__global__ void __launch_bounds__(256) k_bitify(const float* __restrict__ x) {
    extern __shared__ float xs[];                 // [C_IN][T_SEQ]
    int n = blockIdx.x;
    const float* xb = x + (size_t)n * C_IN * T_SEQ;
    for (int i = threadIdx.x; i < C_IN * T_SEQ; i += blockDim.x) xs[i] = xb[i];
    __syncthreads();

    int wrp = threadIdx.x >> 5, lane = threadIdx.x & 31;
    for (int task = wrp; task < 2 * T_SEQ; task += 8) {
        int path = task >= T_SEQ;
        int seq = path ? task - T_SEQ : task;
        unsigned* ob = g_idx + ((size_t)(path * N_BATCH + n) * T_SEQ + seq) * IDX_CAP;

        int pc = 0;
        if (path) {
            int blk = seq / 78, j2 = seq % 78;
            pc = 2 * c_td[j2 >> 1] - 2 + (j2 & 1) + blk * 78;   // PERM[seq]
        }
        int total = 0;
        #pragma unroll
        for (int w = 0; w < 5; w++) {
            int j = w * 32 + lane;
            bool bit = false;
            if (j < C_IN)
                bit = (path ? xs[pc * T_SEQ + j] : xs[j * T_SEQ + seq]) > 0.5f;
            unsigned m = __ballot_sync(0xffffffffu, bit);
            int pos = total + __popc(m & ((1u << lane) - 1u));
            if (bit) ob[pos] = (unsigned)(j * ROW_BYTES);
            total += __popc(m);
        }
        if (lane == 0) {
            while (total & 3) ob[total++] = (unsigned)(C_IN * ROW_BYTES);
            g_cnt[(path * N_BATCH + n) * T_SEQ + seq] = total;
        }
    }
}

// ---------------------------------------------------------------------------
// K1a: sparse GEMM1 for one t-chunk. grid (hb, n, path), 512 threads.
// Weights loaded from pre-transposed g_w1t: coalesced LDG, conflict-free STS.
// ---------------------------------------------------------------------------
__global__ void __launch_bounds__(512) k_gemm1(int t0) {
    extern __shared__ float ws[];   // [157][128]; row 156 = zeros
    int hb = blockIdx.x, n = blockIdx.y, path = blockIdx.z;
    int tid = threadIdx.x;

    const float* wt = g_w1t[path] + hb * HB_SZ;
    for (int i = tid; i < C_IN * HB_SZ; i += 512) {
        int c = i >> 7, hl = i & 127;
        ws[i] = wt[c * H_DIM + hl];
    }
    for (int i = tid; i < HB_SZ; i += 512) ws[C_IN * HB_SZ + i] = 0.0f;
    __syncthreads();

    uint32_t ws32;
    asm("{ .reg .u64 t; cvta.to.shared.u64 t, %1; cvt.u32.u64 %0, t; }"
        : "=r"(ws32) : "l"(ws));

    int wrp = tid >> 5, lane = tid & 31;
    uint32_t base = ws32 + lane * 16;
    float* pp = g_prechunk + (size_t)((path * N_BATCH + n) * HB_CNT + hb) * (CHUNK_T * HB_SZ);
    const int seqbase = (path * N_BATCH + n) * T_SEQ + t0;

    for (int tl = wrp; tl < CHUNK_T; tl += 16) {
        const unsigned* ib = g_idx + (size_t)(seqbase + tl) * IDX_CAP;
        int cnt = g_cnt[seqbase + tl];
        unsigned long long acc0 = 0ULL, acc1 = 0ULL;
        for (int k = 0; k < cnt; k += 4) {
            uint4 v = *(const uint4*)(ib + k);
            unsigned long long a, b;
            asm volatile("ld.shared.v2.b64 {%0,%1}, [%2];" : "=l"(a), "=l"(b) : "r"(base + v.x));
            asm("add.rn.f32x2 %0, %0, %1;" : "+l"(acc0) : "l"(a));
            asm("add.rn.f32x2 %0, %0, %1;" : "+l"(acc1) : "l"(b));
            asm volatile("ld.shared.v2.b64 {%0,%1}, [%2];" : "=l"(a), "=l"(b) : "r"(base + v.y));
            asm("add.rn.f32x2 %0, %0, %1;" : "+l"(acc0) : "l"(a));
            asm("add.rn.f32x2 %0, %0, %1;" : "+l"(acc1) : "l"(b));
            asm volatile("ld.shared.v2.b64 {%0,%1}, [%2];" : "=l"(a), "=l"(b) : "r"(base + v.z));
            asm("add.rn.f32x2 %0, %0, %1;" : "+l"(acc0) : "l"(a));
            asm("add.rn.f32x2 %0, %0, %1;" : "+l"(acc1) : "l"(b));
            asm volatile("ld.shared.v2.b64 {%0,%1}, [%2];" : "=l"(a), "=l"(b) : "r"(base + v.w));
            asm("add.rn.f32x2 %0, %0, %1;" : "+l"(acc0) : "l"(a));
            asm("add.rn.f32x2 %0, %0, %1;" : "+l"(acc1) : "l"(b));
        }
        uint2 u0 = *reinterpret_cast<uint2*>(&acc0);
        uint2 u1 = *reinterpret_cast<uint2*>(&acc1);
        float4 r;
        r.x = __uint_as_float(u0.x); r.y = __uint_as_float(u0.y);
        r.z = __uint_as_float(u1.x); r.w = __uint_as_float(u1.y);
        *(float4*)(pp + tl * HB_SZ + lane * 4) = r;
    }
}

// ---------------------------------------------------------------------------
// K1b: layer-1 recurrence for one chunk; spikes -> bitmasks.
// grid (hb, n, path), 128 threads. State carried in g_stF/g_stH.
// ---------------------------------------------------------------------------
__global__ void __launch_bounds__(HB_SZ) k_neuron1(int chunk) {
    int hb = blockIdx.x, n = blockIdx.y, path = blockIdx.z;
    int tid = threadIdx.x;
    int lane = tid & 31, wrp = tid >> 5;

    int slab = (path * N_BATCH + n) * HB_CNT + hb;
    const float* pp = g_prechunk + (size_t)slab * (CHUNK_T * HB_SZ);
    unsigned* sbout = g_sb + (size_t)slab * (T_SEQ * 4) + (chunk * CHUNK_T) * 4;

    float A, B, P, Q;
    unsigned hist;
    if (chunk == 0) {
        A = B = P = Q = 0.f; hist = 0u;
    } else {
        float4 st = g_stF[slab * HB_SZ + tid];
        A = st.x; B = st.y; P = st.z; Q = st.w;
        hist = g_stH[slab * HB_SZ + tid];
    }

    #pragma unroll 6
    for (int tl = 0; tl < CHUNK_T; tl++) {
        float acc = pp[tl * HB_SZ + tid];
        B = LAM_S * (B + A);
        A = LAM_S * A + acc;
        float u  = K_PSP * B;
        float um = u + C_REF * Q;
        unsigned spk = (um >= THETA) ? 1u : 0u;
        float s = (float)spk;
        float aged = (float)((hist >> 14) & 1u);
        Q = LAM_R * (Q + P + s) - aged * C_Q16;
        P = LAM_R * (P + s)     - aged * C_P16;
        hist = (hist << 1) | spk;
        unsigned bal = __ballot_sync(0xffffffffu, spk);
        if (lane == 0) sbout[tl * 4 + wrp] = bal;
    }

    if (chunk == 0) {
        g_stF[slab * HB_SZ + tid] = make_float4(A, B, P, Q);
        g_stH[slab * HB_SZ + tid] = hist;
    }
}

// ---------------------------------------------------------------------------
// K2: s1 x W2 from bitmasks (per-hb partials summed in ascending hb order),
// then layer-2 recurrence + output. grid 256 = (path, n), 128 threads.
// ---------------------------------------------------------------------------
#define TO (T_SEQ * O_DIM)   // 3120
__global__ void __launch_bounds__(128) k_final(float* __restrict__ out,
                                               const float* __restrict__ wb_main,
                                               const float* __restrict__ wb_loc) {
    extern __shared__ float smem[];
    float* w2s = smem;                   // [1024][20], 80KB
    float* v   = smem + H_DIM * O_DIM;   // [156][20]

    int b = blockIdx.x;
    int path = b >> 7, n = b & 127;
    int tid = threadIdx.x;
    const float* wb = path ? wb_loc : wb_main;

    for (int i = tid; i < H_DIM * O_DIM; i += 128) {
        int o = i / H_DIM, h = i % H_DIM;
        w2s[h * O_DIM + o] = wb[(size_t)o * H_DIM + h];
    }
    __syncthreads();

    uint32_t w2s32;
    asm("{ .reg .u64 t; cvta.to.shared.u64 t, %1; cvt.u32.u64 %0, t; }"
        : "=r"(w2s32) : "l"(w2s));

    const unsigned* sbb = g_sb + (size_t)(path * N_BATCH + n) * HB_CNT * (T_SEQ * 4);

    for (int t = tid; t < T_SEQ; t += 128) {
        unsigned long long acc[10];
        #pragma unroll
        for (int i = 0; i < 10; i++) acc[i] = 0ULL;
        for (int hb = 0; hb < HB_CNT; hb++) {
            unsigned long long tmp[10];
            #pragma unroll
            for (int i = 0; i < 10; i++) tmp[i] = 0ULL;
            const unsigned* sm = sbb + (size_t)hb * (T_SEQ * 4) + t * 4;
            uint32_t hbbase = w2s32 + (unsigned)(hb * HB_SZ * O_DIM * 4);
            #pragma unroll
            for (int wd = 0; wd < 4; wd++) {
                unsigned m = sm[wd];
                while (m) {
                    int j = __ffs(m) - 1;
                    m &= m - 1u;
                    uint32_t row = hbbase + (unsigned)((wd * 32 + j) * (O_DIM * 4));
                    unsigned long long a, c;
                    asm volatile("ld.shared.v2.b64 {%0,%1}, [%2];" : "=l"(a), "=l"(c) : "r"(row));
                    asm("add.rn.f32x2 %0, %0, %1;" : "+l"(tmp[0]) : "l"(a));
                    asm("add.rn.f32x2 %0, %0, %1;" : "+l"(tmp[1]) : "l"(c));
                    asm volatile("ld.shared.v2.b64 {%0,%1}, [%2];" : "=l"(a), "=l"(c) : "r"(row + 16));
                    asm("add.rn.f32x2 %0, %0, %1;" : "+l"(tmp[2]) : "l"(a));
                    asm("add.rn.f32x2 %0, %0, %1;" : "+l"(tmp[3]) : "l"(c));
                    asm volatile("ld.shared.v2.b64 {%0,%1}, [%2];" : "=l"(a), "=l"(c) : "r"(row + 32));
                    asm("add.rn.f32x2 %0, %0, %1;" : "+l"(tmp[4]) : "l"(a));
                    asm("add.rn.f32x2 %0, %0, %1;" : "+l"(tmp[5]) : "l"(c));
                    asm volatile("ld.shared.v2.b64 {%0,%1}, [%2];" : "=l"(a), "=l"(c) : "r"(row + 48));
                    asm("add.rn.f32x2 %0, %0, %1;" : "+l"(tmp[6]) : "l"(a));
                    asm("add.rn.f32x2 %0, %0, %1;" : "+l"(tmp[7]) : "l"(c));
                    asm volatile("ld.shared.v2.b64 {%0,%1}, [%2];" : "=l"(a), "=l"(c) : "r"(row + 64));
                    asm("add.rn.f32x2 %0, %0, %1;" : "+l"(tmp[8]) : "l"(a));
                    asm("add.rn.f32x2 %0, %0, %1;" : "+l"(tmp[9]) : "l"(c));
                }
            }
            #pragma unroll
            for (int i = 0; i < 10; i++)
                asm("add.rn.f32x2 %0, %0, %1;" : "+l"(acc[i]) : "l"(tmp[i]));
        }
        float2* vp = (float2*)(v + t * O_DIM);
        #pragma unroll
        for (int i = 0; i < 10; i++) vp[i] = *reinterpret_cast<float2*>(&acc[i]);
    }
    __syncthreads();

    if (tid < O_DIM) {
        int o = tid;
        float* op = out + ((size_t)n * O_DIM + o) * 312 + path * T_SEQ;
        float A = 0.f, B = 0.f, P = 0.f, Q = 0.f;
        unsigned hist = 0u;
        #pragma unroll 4
        for (int t = 0; t < T_SEQ; t++) {
            float pre = v[t * O_DIM + o];
            B = LAM_S * (B + A);
            A = LAM_S * A + pre;
            float u  = K_PSP * B;
            float um = u + C_REF * Q;
            unsigned spk = (um >= THETA) ? 1u : 0u;
            float s = (float)spk;
            float aged = (float)((hist >> 14) & 1u);
            Q = LAM_R * (Q + P + s) - aged * C_Q16;
            P = LAM_R * (P + s)     - aged * C_P16;
            hist = (hist << 1) | spk;
            op[t] = s;
        }
    }
}

// ---------------------------------------------------------------------------
extern "C" void kernel_launch(void* const* d_in, const int* in_sizes, int n_in,
                              void* d_out, int out_size) {
    const float* x   = (const float*)d_in[0];
    const float* w1  = (const float*)d_in[1];
    const float* w2  = (const float*)d_in[2];
    const float* wl1 = (const float*)d_in[3];
    const float* wl2 = (const float*)d_in[4];
    float* out = (float*)d_out;

    const int SM0 = C_IN * T_SEQ * 4;                    // 97344
    const int SM1 = 157 * HB_SZ * 4;                     // 80384
    const int SM2 = (H_DIM * O_DIM + TO) * 4;            // 94400
    cudaFuncSetAttribute(k_bitify, cudaFuncAttributeMaxDynamicSharedMemorySize, SM0);
    cudaFuncSetAttribute(k_gemm1,  cudaFuncAttributeMaxDynamicSharedMemorySize, SM1);
    cudaFuncSetAttribute(k_final,  cudaFuncAttributeMaxDynamicSharedMemorySize, SM2);

    k_wt<<<(2 * C_IN * H_DIM + 255) / 256, 256>>>(w1, wl1);
    k_bitify<<<N_BATCH, 256, SM0>>>(x);

    dim3 g1(HB_CNT, N_BATCH, 2);
    k_gemm1<<<g1, 512, SM1>>>(0);
    k_neuron1<<<g1, HB_SZ>>>(0);
    k_gemm1<<<g1, 512, SM1>>>(CHUNK_T);
    k_neuron1<<<g1, HB_SZ>>>(1);

    k_final<<<2 * N_BATCH, 128, SM2>>>(out, w2, wl2);
}

// round 8
// speedup vs baseline: 1.8958x; 1.1579x over previous
#include <cuda_runtime.h>
#include <cstdint>

// ---------------------------------------------------------------------------
// LocationSlayerArch, round 8: round-7 + 8-sample weight-tile amortization
// (gemm = 256 blocks = one full wave; weight L2 traffic /8) so g_prechunk
// stays L2-resident for neuron.
//   k_wt     : W1/Wl1 -> g_w1t[path][c][h] (one-time)
//   k_bitify : ballot-compacted active-index lists
//   k_gemm1  : sparse layer-1 GEMM per t-chunk -> g_prechunk (L2-resident)
//   k_neuron1: psp+spike recurrence per chunk -> bitmasks g_sb
//   k_final  : s1 x W2 GEMM from bitmasks + layer-2 recurrence + output
// ---------------------------------------------------------------------------

#define N_BATCH 128
#define T_SEQ   156
#define C_IN    156
#define H_DIM   1024
#define O_DIM   20
#define HB_CNT  8
#define HB_SZ   128
#define IDX_CAP 160
#define ROW_BYTES 512                 // ws row stride (128 floats)
#define CHUNK_T 78                    // 156 = 2 * 78
#define NGRP    8                     // batch samples per gemm block

#define LAM_S  0.90483741803595952f
#define K_PSP  0.27182818284590452f
#define LAM_R  0.36787944117144233f
#define C_REF  -54.365636569180902f
#define C_P16  1.1253517471925912e-07f
#define C_Q16  1.8005627955081459e-06f
#define THETA  10.0f

__device__ __constant__ int c_td[39] = {
    11,25,35,4,18,30,7,2,20,37,29,12,9,33,23,16,1,6,15,21,
    27,34,39,24,17,10,31,38,28,14,3,22,32,8,19,36,5,13,26};

#define NSLAB (2 * N_BATCH * HB_CNT)          // 2048 (path,n,hb) slabs
__device__ unsigned g_idx[(size_t)2 * N_BATCH * T_SEQ * IDX_CAP];   // 25.6MB
__device__ int      g_cnt[2 * N_BATCH * T_SEQ];
__device__ float    g_w1t[2][C_IN * H_DIM];                         // 1.3MB
__device__ float    g_prechunk[(size_t)NSLAB * CHUNK_T * HB_SZ];    // 81.8MB
__device__ float4   g_stF[NSLAB * HB_SZ];
__device__ unsigned g_stH[NSLAB * HB_SZ];
__device__ unsigned g_sb[(size_t)NSLAB * T_SEQ * 4];                // 5.1MB

// ---------------------------------------------------------------------------
// K-1: transpose layer-1 weights: g_w1t[path][c*1024 + h] = w[h*156 + c].
// ---------------------------------------------------------------------------
__global__ void __launch_bounds__(256) k_wt(const float* __restrict__ w_main,
                                            const float* __restrict__ w_loc) {
    int i = blockIdx.x * 256 + threadIdx.x;
    if (i >= 2 * C_IN * H_DIM) return;
    int path = i / (C_IN * H_DIM);
    int r = i % (C_IN * H_DIM);
    int c = r / H_DIM, h = r % H_DIM;
    const float* w = path ? w_loc : w_main;
    g_w1t[path][r] = w[(size_t)h * C_IN + c];
}

// ---------------------------------------------------------------------------
// K0: ballot-compacted active-index lists. grid n, 256 threads = 8 warps.
// ---------------------------------------------------------------------------
__global__ void __launch_bounds__(256) k_bitify(const float* __restrict__ x) {
    extern __shared__ float xs[];                 // [C_IN][T_SEQ]
    int n = blockIdx.x;
    const float* xb = x + (size_t)n * C_IN * T_SEQ;
    for (int i = threadIdx.x; i < C_IN * T_SEQ; i += blockDim.x) xs[i] = xb[i];
    __syncthreads();

    int wrp = threadIdx.x >> 5, lane = threadIdx.x & 31;
    for (int task = wrp; task < 2 * T_SEQ; task += 8) {
        int path = task >= T_SEQ;
        int seq = path ? task - T_SEQ : task;
        unsigned* ob = g_idx + ((size_t)(path * N_BATCH + n) * T_SEQ + seq) * IDX_CAP;

        int pc = 0;
        if (path) {
            int blk = seq / 78, j2 = seq % 78;
            pc = 2 * c_td[j2 >> 1] - 2 + (j2 & 1) + blk * 78;   // PERM[seq]
        }
        int total = 0;
        #pragma unroll
        for (int w = 0; w < 5; w++) {
            int j = w * 32 + lane;
            bool bit = false;
            if (j < C_IN)
                bit = (path ? xs[pc * T_SEQ + j] : xs[j * T_SEQ + seq]) > 0.5f;
            unsigned m = __ballot_sync(0xffffffffu, bit);
            int pos = total + __popc(m & ((1u << lane) - 1u));
            if (bit) ob[pos] = (unsigned)(j * ROW_BYTES);
            total += __popc(m);
        }
        if (lane == 0) {
            while (total & 3) ob[total++] = (unsigned)(C_IN * ROW_BYTES);
            g_cnt[(path * N_BATCH + n) * T_SEQ + seq] = total;
        }
    }
}

// ---------------------------------------------------------------------------
// K1a: sparse GEMM1 for one t-chunk. grid (hb, N/8, path) = 256 blocks,
// 512 threads = 16 warps. Warp w: n = ngrp*8 + (w>>1), t strided by 2.
// Weight tile loaded once per block, serves 8 batch samples.
// ---------------------------------------------------------------------------
__global__ void __launch_bounds__(512) k_gemm1(int t0) {
    extern __shared__ float ws[];   // [157][128]; row 156 = zeros
    int hb = blockIdx.x, ng = blockIdx.y, path = blockIdx.z;
    int tid = threadIdx.x;

    const float* wt = g_w1t[path] + hb * HB_SZ;
    for (int i = tid; i < C_IN * HB_SZ; i += 512) {
        int c = i >> 7, hl = i & 127;
        ws[i] = wt[c * H_DIM + hl];
    }
    for (int i = tid; i < HB_SZ; i += 512) ws[C_IN * HB_SZ + i] = 0.0f;
    __syncthreads();

    uint32_t ws32;
    asm("{ .reg .u64 t; cvta.to.shared.u64 t, %1; cvt.u32.u64 %0, t; }"
        : "=r"(ws32) : "l"(ws));

    int wrp = tid >> 5, lane = tid & 31;
    uint32_t base = ws32 + lane * 16;
    int n = ng * NGRP + (wrp >> 1);
    float* pp = g_prechunk + (size_t)((path * N_BATCH + n) * HB_CNT + hb) * (CHUNK_T * HB_SZ);
    const int seqbase = (path * N_BATCH + n) * T_SEQ + t0;

    for (int tl = (wrp & 1); tl < CHUNK_T; tl += 2) {
        const unsigned* ib = g_idx + (size_t)(seqbase + tl) * IDX_CAP;
        int cnt = g_cnt[seqbase + tl];
        unsigned long long acc0 = 0ULL, acc1 = 0ULL;
        for (int k = 0; k < cnt; k += 4) {
            uint4 v = *(const uint4*)(ib + k);
            unsigned long long a, b;
            asm volatile("ld.shared.v2.b64 {%0,%1}, [%2];" : "=l"(a), "=l"(b) : "r"(base + v.x));
            asm("add.rn.f32x2 %0, %0, %1;" : "+l"(acc0) : "l"(a));
            asm("add.rn.f32x2 %0, %0, %1;" : "+l"(acc1) : "l"(b));
            asm volatile("ld.shared.v2.b64 {%0,%1}, [%2];" : "=l"(a), "=l"(b) : "r"(base + v.y));
            asm("add.rn.f32x2 %0, %0, %1;" : "+l"(acc0) : "l"(a));
            asm("add.rn.f32x2 %0, %0, %1;" : "+l"(acc1) : "l"(b));
            asm volatile("ld.shared.v2.b64 {%0,%1}, [%2];" : "=l"(a), "=l"(b) : "r"(base + v.z));
            asm("add.rn.f32x2 %0, %0, %1;" : "+l"(acc0) : "l"(a));
            asm("add.rn.f32x2 %0, %0, %1;" : "+l"(acc1) : "l"(b));
            asm volatile("ld.shared.v2.b64 {%0,%1}, [%2];" : "=l"(a), "=l"(b) : "r"(base + v.w));
            asm("add.rn.f32x2 %0, %0, %1;" : "+l"(acc0) : "l"(a));
            asm("add.rn.f32x2 %0, %0, %1;" : "+l"(acc1) : "l"(b));
        }
        uint2 u0 = *reinterpret_cast<uint2*>(&acc0);
        uint2 u1 = *reinterpret_cast<uint2*>(&acc1);
        float4 r;
        r.x = __uint_as_float(u0.x); r.y = __uint_as_float(u0.y);
        r.z = __uint_as_float(u1.x); r.w = __uint_as_float(u1.y);
        *(float4*)(pp + tl * HB_SZ + lane * 4) = r;
    }
}

// ---------------------------------------------------------------------------
// K1b: layer-1 recurrence for one chunk; spikes -> bitmasks.
// grid (hb, n, path), 128 threads. State carried in g_stF/g_stH.
// ---------------------------------------------------------------------------
__global__ void __launch_bounds__(HB_SZ) k_neuron1(int chunk) {
    int hb = blockIdx.x, n = blockIdx.y, path = blockIdx.z;
    int tid = threadIdx.x;
    int lane = tid & 31, wrp = tid >> 5;

    int slab = (path * N_BATCH + n) * HB_CNT + hb;
    const float* pp = g_prechunk + (size_t)slab * (CHUNK_T * HB_SZ);
    unsigned* sbout = g_sb + (size_t)slab * (T_SEQ * 4) + (chunk * CHUNK_T) * 4;

    float A, B, P, Q;
    unsigned hist;
    if (chunk == 0) {
        A = B = P = Q = 0.f; hist = 0u;
    } else {
        float4 st = g_stF[slab * HB_SZ + tid];
        A = st.x; B = st.y; P = st.z; Q = st.w;
        hist = g_stH[slab * HB_SZ + tid];
    }

    #pragma unroll 6
    for (int tl = 0; tl < CHUNK_T; tl++) {
        float acc = pp[tl * HB_SZ + tid];
        B = LAM_S * (B + A);
        A = LAM_S * A + acc;
        float u  = K_PSP * B;
        float um = u + C_REF * Q;
        unsigned spk = (um >= THETA) ? 1u : 0u;
        float s = (float)spk;
        float aged = (float)((hist >> 14) & 1u);
        Q = LAM_R * (Q + P + s) - aged * C_Q16;
        P = LAM_R * (P + s)     - aged * C_P16;
        hist = (hist << 1) | spk;
        unsigned bal = __ballot_sync(0xffffffffu, spk);
        if (lane == 0) sbout[tl * 4 + wrp] = bal;
    }

    if (chunk == 0) {
        g_stF[slab * HB_SZ + tid] = make_float4(A, B, P, Q);
        g_stH[slab * HB_SZ + tid] = hist;
    }
}

// ---------------------------------------------------------------------------
// K2: s1 x W2 from bitmasks (per-hb partials summed in ascending hb order),
// then layer-2 recurrence + output. grid 256 = (path, n), 256 threads.
// ---------------------------------------------------------------------------
#define TO (T_SEQ * O_DIM)   // 3120
__global__ void __launch_bounds__(256) k_final(float* __restrict__ out,
                                               const float* __restrict__ wb_main,
                                               const float* __restrict__ wb_loc) {
    extern __shared__ float smem[];
    float* w2s = smem;                   // [1024][20], 80KB
    float* v   = smem + H_DIM * O_DIM;   // [156][20]

    int b = blockIdx.x;
    int path = b >> 7, n = b & 127;
    int tid = threadIdx.x;
    const float* wb = path ? wb_loc : wb_main;

    for (int i = tid; i < H_DIM * O_DIM; i += 256) {
        int o = i / H_DIM, h = i % H_DIM;
        w2s[h * O_DIM + o] = wb[(size_t)o * H_DIM + h];
    }
    __syncthreads();

    uint32_t w2s32;
    asm("{ .reg .u64 t; cvta.to.shared.u64 t, %1; cvt.u32.u64 %0, t; }"
        : "=r"(w2s32) : "l"(w2s));

    const unsigned* sbb = g_sb + (size_t)(path * N_BATCH + n) * HB_CNT * (T_SEQ * 4);

    for (int t = tid; t < T_SEQ; t += 256) {
        unsigned long long acc[10];
        #pragma unroll
        for (int i = 0; i < 10; i++) acc[i] = 0ULL;
        for (int hb = 0; hb < HB_CNT; hb++) {
            unsigned long long tmp[10];
            #pragma unroll
            for (int i = 0; i < 10; i++) tmp[i] = 0ULL;
            const unsigned* sm = sbb + (size_t)hb * (T_SEQ * 4) + t * 4;
            uint32_t hbbase = w2s32 + (unsigned)(hb * HB_SZ * O_DIM * 4);
            #pragma unroll
            for (int wd = 0; wd < 4; wd++) {
                unsigned m = sm[wd];
                while (m) {
                    int j = __ffs(m) - 1;
                    m &= m - 1u;
                    uint32_t row = hbbase + (unsigned)((wd * 32 + j) * (O_DIM * 4));
                    unsigned long long a, c;
                    asm volatile("ld.shared.v2.b64 {%0,%1}, [%2];" : "=l"(a), "=l"(c) : "r"(row));
                    asm("add.rn.f32x2 %0, %0, %1;" : "+l"(tmp[0]) : "l"(a));
                    asm("add.rn.f32x2 %0, %0, %1;" : "+l"(tmp[1]) : "l"(c));
                    asm volatile("ld.shared.v2.b64 {%0,%1}, [%2];" : "=l"(a), "=l"(c) : "r"(row + 16));
                    asm("add.rn.f32x2 %0, %0, %1;" : "+l"(tmp[2]) : "l"(a));
                    asm("add.rn.f32x2 %0, %0, %1;" : "+l"(tmp[3]) : "l"(c));
                    asm volatile("ld.shared.v2.b64 {%0,%1}, [%2];" : "=l"(a), "=l"(c) : "r"(row + 32));
                    asm("add.rn.f32x2 %0, %0, %1;" : "+l"(tmp[4]) : "l"(a));
                    asm("add.rn.f32x2 %0, %0, %1;" : "+l"(tmp[5]) : "l"(c));
                    asm volatile("ld.shared.v2.b64 {%0,%1}, [%2];" : "=l"(a), "=l"(c) : "r"(row + 48));
                    asm("add.rn.f32x2 %0, %0, %1;" : "+l"(tmp[6]) : "l"(a));
                    asm("add.rn.f32x2 %0, %0, %1;" : "+l"(tmp[7]) : "l"(c));
                    asm volatile("ld.shared.v2.b64 {%0,%1}, [%2];" : "=l"(a), "=l"(c) : "r"(row + 64));
                    asm("add.rn.f32x2 %0, %0, %1;" : "+l"(tmp[8]) : "l"(a));
                    asm("add.rn.f32x2 %0, %0, %1;" : "+l"(tmp[9]) : "l"(c));
                }
            }
            #pragma unroll
            for (int i = 0; i < 10; i++)
                asm("add.rn.f32x2 %0, %0, %1;" : "+l"(acc[i]) : "l"(tmp[i]));
        }
        float2* vp = (float2*)(v + t * O_DIM);
        #pragma unroll
        for (int i = 0; i < 10; i++) vp[i] = *reinterpret_cast<float2*>(&acc[i]);
    }
    __syncthreads();

    if (tid < O_DIM) {
        int o = tid;
        float* op = out + ((size_t)n * O_DIM + o) * 312 + path * T_SEQ;
        float A = 0.f, B = 0.f, P = 0.f, Q = 0.f;
        unsigned hist = 0u;
        #pragma unroll 4
        for (int t = 0; t < T_SEQ; t++) {
            float pre = v[t * O_DIM + o];
            B = LAM_S * (B + A);
            A = LAM_S * A + pre;
            float u  = K_PSP * B;
            float um = u + C_REF * Q;
            unsigned spk = (um >= THETA) ? 1u : 0u;
            float s = (float)spk;
            float aged = (float)((hist >> 14) & 1u);
            Q = LAM_R * (Q + P + s) - aged * C_Q16;
            P = LAM_R * (P + s)     - aged * C_P16;
            hist = (hist << 1) | spk;
            op[t] = s;
        }
    }
}

// ---------------------------------------------------------------------------
extern "C" void kernel_launch(void* const* d_in, const int* in_sizes, int n_in,
                              void* d_out, int out_size) {
    const float* x   = (const float*)d_in[0];
    const float* w1  = (const float*)d_in[1];
    const float* w2  = (const float*)d_in[2];
    const float* wl1 = (const float*)d_in[3];
    const float* wl2 = (const float*)d_in[4];
    float* out = (float*)d_out;

    const int SM0 = C_IN * T_SEQ * 4;                    // 97344
    const int SM1 = 157 * HB_SZ * 4;                     // 80384
    const int SM2 = (H_DIM * O_DIM + TO) * 4;            // 94400
    cudaFuncSetAttribute(k_bitify, cudaFuncAttributeMaxDynamicSharedMemorySize, SM0);
    cudaFuncSetAttribute(k_gemm1,  cudaFuncAttributeMaxDynamicSharedMemorySize, SM1);
    cudaFuncSetAttribute(k_final,  cudaFuncAttributeMaxDynamicSharedMemorySize, SM2);

    k_wt<<<(2 * C_IN * H_DIM + 255) / 256, 256>>>(w1, wl1);
    k_bitify<<<N_BATCH, 256, SM0>>>(x);

    dim3 gg(HB_CNT, N_BATCH / NGRP, 2);
    dim3 gn(HB_CNT, N_BATCH, 2);
    k_gemm1<<<gg, 512, SM1>>>(0);
    k_neuron1<<<gn, HB_SZ>>>(0);
    k_gemm1<<<gg, 512, SM1>>>(CHUNK_T);
    k_neuron1<<<gn, HB_SZ>>>(1);

    k_final<<<2 * N_BATCH, 256, SM2>>>(out, w2, wl2);
}